// round 2
// baseline (speedup 1.0000x reference)
#include <cuda_runtime.h>
#include <cstdint>
#include <cstddef>

// ---------------------------------------------------------------------------
// MessagePassing: h evolves over 4 steps of (3 message passes + GRU).
//
// Restructured as:
//   transform:  T[v, c] = sum_j x[v,j] * Wrow_c[j]      (dense GEMM, c = k*64+i,
//               plus one extra 64-col group sourced from b => the xn@B^T term)
//   scatter:    for each edge: m[i] = T[src, K*64+i] + sum_k feat[e,k]*T[src,k*64+i]
//               atomicAdd into out[dst, i]
//   GRU pass1:  gi = a @ wi^T + bi   (same GEMM kernel, transposed output [192][N])
//   GRU pass2:  gh dots + gates, fused, h-row in registers
// ---------------------------------------------------------------------------

#define TILE_A 128
#define TILE_N 32
#define MAX_ATOMS 30720

// scratch (device globals: allocation-free contract)
__device__ float g_h [(size_t)MAX_ATOMS * 64];
__device__ float g_a [(size_t)MAX_ATOMS * 64];
__device__ float g_b [(size_t)MAX_ATOMS * 64];
__device__ float g_T [(size_t)MAX_ATOMS * 1088];   // max (16+1)*64 cols
__device__ float g_gi[(size_t)MAX_ATOMS * 192];    // GRU pass1, transposed [192][N]

// ---------------------------------------------------------------------------
// transform: T = X @ W^T  (row c of the effective weight = W1[c*64..] for
// c < ncols1 else W2[(c-ncols1)*64..]).  Optional bias (GRU pass1), optional
// transposed output, optional zeroing of the scatter accumulator.
// ---------------------------------------------------------------------------
template <bool TRANS>
__global__ void __launch_bounds__(TILE_A)
transform_kernel(const float* __restrict__ X,
                 const float* __restrict__ W1, int ncols1,
                 const float* __restrict__ W2,
                 const float* __restrict__ bias,
                 float* __restrict__ T, int tpitch,
                 float* __restrict__ zero_out,
                 int natoms)
{
    __shared__ float Xs[TILE_A * 65];          // X tile, pad 65 (conflict-free row reads)
    __shared__ float Ws[TILE_N * 64];          // weight tile (uniform broadcast reads)
    float* stage = Xs;                          // reuse as output stage, stride 33

    const int tid = threadIdx.x;
    const int a0  = blockIdx.x * TILE_A;
    const int c0  = blockIdx.y * TILE_N;

    // cooperative, coalesced X tile load
    for (int idx = tid; idx < TILE_A * 64; idx += TILE_A) {
        int r = idx >> 6, j = idx & 63;
        int v = a0 + r;
        Xs[r * 65 + j] = (v < natoms) ? X[(size_t)v * 64 + j] : 0.f;
    }
    __syncthreads();

    // this thread's atom row -> registers
    float x[64];
#pragma unroll
    for (int j = 0; j < 64; ++j) x[j] = Xs[tid * 65 + j];

    // weight tile load (coalesced; rows of W are contiguous 64-float blocks)
    for (int idx = tid; idx < TILE_N * 64; idx += TILE_A) {
        int c = idx >> 6, j = idx & 63;
        int cg = c0 + c;
        const float* src = (cg < ncols1) ? (W1 + (size_t)cg * 64)
                                         : (W2 + (size_t)(cg - ncols1) * 64);
        Ws[c * 64 + j] = src[j];
    }
    __syncthreads();   // also guarantees all reg-copies done before stage overwrite

    for (int c = 0; c < TILE_N; ++c) {
        const float4* w4 = reinterpret_cast<const float4*>(Ws + c * 64);
        float acc = bias ? bias[c0 + c] : 0.f;
#pragma unroll
        for (int j4 = 0; j4 < 16; ++j4) {
            float4 w = w4[j4];                      // uniform across warp -> broadcast LDS.128
            acc = fmaf(x[4 * j4 + 0], w.x, acc);
            acc = fmaf(x[4 * j4 + 1], w.y, acc);
            acc = fmaf(x[4 * j4 + 2], w.z, acc);
            acc = fmaf(x[4 * j4 + 3], w.w, acc);
        }
        stage[tid * 33 + c] = acc;                  // stride 33: conflict-free
    }
    __syncthreads();

    if (TRANS) {
        // write T[c][atom] (column-major over atoms) — coalesced over atoms
        for (int idx = tid; idx < TILE_A * TILE_N; idx += TILE_A) {
            int c = idx >> 7;          // idx % 128 == tid
            int v = a0 + tid;
            if (v < natoms) T[(size_t)(c0 + c) * natoms + v] = stage[tid * 33 + c];
        }
    } else {
        for (int idx = tid; idx < TILE_A * TILE_N; idx += TILE_A) {
            int r = idx >> 5, c = idx & 31;
            int v = a0 + r;
            if (v < natoms) T[(size_t)v * tpitch + c0 + c] = stage[r * 33 + c];
        }
    }

    // zero the next scatter accumulator (only column-tile 0 blocks)
    if (zero_out != nullptr && c0 == 0) {
        for (int idx = tid; idx < TILE_A * 64; idx += TILE_A) {
            int r = idx >> 6, j = idx & 63;
            int v = a0 + r;
            if (v < natoms) zero_out[(size_t)v * 64 + j] = 0.f;
        }
    }
}

// ---------------------------------------------------------------------------
// scatter: 64 threads per edge (lane i = output dim), 4 edges per block.
// m[i] = T[src, KF*64+i] (the b-column, weight 1) + sum_k feat[e,k]*T[src,k*64+i]
// ---------------------------------------------------------------------------
template <int KF>
__global__ void __launch_bounds__(256)
scatter_kernel(const float* __restrict__ T, int tpitch,
               const float* __restrict__ feat,
               const int*   __restrict__ idx,
               float*       __restrict__ out,
               int nedges)
{
    const int tid = threadIdx.x;
    const int g = tid >> 6, i = tid & 63;
    const int e = blockIdx.x * 4 + g;
    if (e >= nedges) return;

    const int src = __ldg(&idx[2 * e + 1]);
    const int dst = __ldg(&idx[2 * e + 0]);
    const float* trow = T + (size_t)src * tpitch;

    float f[KF];
#pragma unroll
    for (int kk = 0; kk < KF; ++kk) f[kk] = __ldg(&feat[(size_t)e * KF + kk]);

    float m = __ldg(&trow[KF * 64 + i]);         // b-term column, weight 1
#pragma unroll
    for (int kk = 0; kk < KF; ++kk)
        m = fmaf(f[kk], __ldg(&trow[kk * 64 + i]), m);

    atomicAdd(&out[(size_t)dst * 64 + i], m);
}

// ---------------------------------------------------------------------------
// GRU pass2: per-atom thread; hprev row in registers; gh dots via uniform
// float4 LDG of wh (L1-resident, 48KB); gi gathered coalesced from the
// transposed pass1 output.
// ---------------------------------------------------------------------------
__global__ void __launch_bounds__(TILE_A)
gru_pass2_kernel(const float* __restrict__ hprev,
                 const float* __restrict__ giT,   // [192][natoms], includes bi
                 const float* __restrict__ wh,    // [192][64]
                 const float* __restrict__ bh,    // [192]
                 float* __restrict__ hout,
                 int natoms)
{
    __shared__ float Xs[TILE_A * 65];
    const int tid = threadIdx.x;
    const int a0  = blockIdx.x * TILE_A;

    for (int idx = tid; idx < TILE_A * 64; idx += TILE_A) {
        int r = idx >> 6, j = idx & 63;
        int v = a0 + r;
        Xs[r * 65 + j] = (v < natoms) ? hprev[(size_t)v * 64 + j] : 0.f;
    }
    __syncthreads();

    float x[64];
#pragma unroll
    for (int j = 0; j < 64; ++j) x[j] = Xs[tid * 65 + j];

    const int v  = a0 + tid;
    const int vv = (v < natoms) ? v : 0;

    for (int i = 0; i < 64; ++i) {
        float ar = bh[i], az = bh[64 + i], an = bh[128 + i];
        const float4* wr = reinterpret_cast<const float4*>(wh + (size_t)i * 64);
        const float4* wz = reinterpret_cast<const float4*>(wh + (size_t)(64 + i) * 64);
        const float4* wn = reinterpret_cast<const float4*>(wh + (size_t)(128 + i) * 64);
#pragma unroll
        for (int j4 = 0; j4 < 16; ++j4) {
            float4 a4 = wr[j4], b4 = wz[j4], c4 = wn[j4];
            ar = fmaf(x[4*j4+0], a4.x, ar); ar = fmaf(x[4*j4+1], a4.y, ar);
            ar = fmaf(x[4*j4+2], a4.z, ar); ar = fmaf(x[4*j4+3], a4.w, ar);
            az = fmaf(x[4*j4+0], b4.x, az); az = fmaf(x[4*j4+1], b4.y, az);
            az = fmaf(x[4*j4+2], b4.z, az); az = fmaf(x[4*j4+3], b4.w, az);
            an = fmaf(x[4*j4+0], c4.x, an); an = fmaf(x[4*j4+1], c4.y, an);
            an = fmaf(x[4*j4+2], c4.z, an); an = fmaf(x[4*j4+3], c4.w, an);
        }
        float gir = giT[(size_t)i         * natoms + vv];
        float giz = giT[(size_t)(64 + i)  * natoms + vv];
        float gin = giT[(size_t)(128 + i) * natoms + vv];

        float r_ = 1.f / (1.f + __expf(-(gir + ar)));
        float z_ = 1.f / (1.f + __expf(-(giz + az)));
        float n_ = tanhf(gin + r_ * an);
        Xs[tid * 65 + i] = (1.f - z_) * n_ + z_ * x[i];   // own row only: no hazard
    }
    __syncthreads();

    for (int idx = tid; idx < TILE_A * 64; idx += TILE_A) {
        int r = idx >> 6, j = idx & 63;
        int v2 = a0 + r;
        if (v2 < natoms) hout[(size_t)v2 * 64 + j] = Xs[r * 65 + j];
    }
}

// ---------------------------------------------------------------------------
extern "C" void kernel_launch(void* const* d_in, const int* in_sizes, int n_in,
                              void* d_out, int out_size)
{
    const float* atom  = (const float*)d_in[0];
    const float* bf    = (const float*)d_in[1];
    const int*   bidx  = (const int*)  d_in[2];
    const float* anf   = (const float*)d_in[3];
    const int*   anidx = (const int*)  d_in[4];
    const float* dif   = (const float*)d_in[5];
    const int*   diidx = (const int*)  d_in[6];
    const float* We    = (const float*)d_in[7];
    const float* be    = (const float*)d_in[8];
    const float* Wa    = (const float*)d_in[9];
    const float* ba    = (const float*)d_in[10];
    const float* Wd    = (const float*)d_in[11];
    const float* bd    = (const float*)d_in[12];
    const float* wi    = (const float*)d_in[13];
    const float* wh    = (const float*)d_in[14];
    const float* bi    = (const float*)d_in[15];
    const float* bh    = (const float*)d_in[16];
    float* out = (float*)d_out;

    const int natoms = in_sizes[0] / 64;
    const int nb = in_sizes[2] / 2;
    const int na = in_sizes[4] / 2;
    const int nd = in_sizes[6] / 2;

    float *pH, *pA, *pB, *pT, *pGI;
    cudaGetSymbolAddress((void**)&pH,  g_h);
    cudaGetSymbolAddress((void**)&pA,  g_a);
    cudaGetSymbolAddress((void**)&pB,  g_b);
    cudaGetSymbolAddress((void**)&pT,  g_T);
    cudaGetSymbolAddress((void**)&pGI, g_gi);

    const int ablocks = (natoms + TILE_A - 1) / TILE_A;
    dim3 blk(TILE_A);

    for (int s = 0; s < 4; ++s) {
        const float* hx = (s == 0) ? atom : pH;

        // ---- message: bonds (k=16, 17*64 = 1088 cols) ----
        transform_kernel<false><<<dim3(ablocks, 1088 / 32), blk>>>(
            hx, We, 16 * 64, be, nullptr, pT, 1088, pA, natoms);
        scatter_kernel<16><<<(nb + 3) / 4, 256>>>(pT, 1088, bf, bidx, pA, nb);

        // ---- message: angles (k=8, 576 cols) ----
        transform_kernel<false><<<dim3(ablocks, 576 / 32), blk>>>(
            pA, Wa, 8 * 64, ba, nullptr, pT, 576, pB, natoms);
        scatter_kernel<8><<<(na + 3) / 4, 256>>>(pT, 576, anf, anidx, pB, na);

        // ---- message: dihedrals (k=12, 832 cols) ----
        transform_kernel<false><<<dim3(ablocks, 832 / 32), blk>>>(
            pB, Wd, 12 * 64, bd, nullptr, pT, 832, pA, natoms);
        scatter_kernel<12><<<(nd + 3) / 4, 256>>>(pT, 832, dif, diidx, pA, nd);

        // ---- GRU ----
        transform_kernel<true><<<dim3(ablocks, 192 / 32), blk>>>(
            pA, wi, 192, nullptr, bi, pGI, 0, nullptr, natoms);
        float* hout = (s == 3) ? out : pH;
        gru_pass2_kernel<<<ablocks, blk>>>(hx, pGI, wh, bh, hout, natoms);
    }
}